// round 1
// baseline (speedup 1.0000x reference)
#include <cuda_runtime.h>
#include <cstdint>
#include <cstddef>

// Problem constants (fixed by setup_inputs)
#define BB 2
#define NN 2048
#define DD 1024
#define HH 16
#define DH 64
#define RR (BB*NN)   // 4096 total rows
#define MM 2048      // kv length (start_pos = 0)
#define BUD 1024
#define BIGV (1<<30)

// ---------------- scratch (device globals; no allocation allowed) ----------------
__device__ float g_Yq[(size_t)RR*DD];
__device__ float g_Yk[(size_t)RR*DD];
__device__ float g_Q[(size_t)BB*HH*NN*DH];
__device__ float g_K[(size_t)BB*HH*NN*DH];
__device__ float g_V[(size_t)BB*HH*NN*DH];
__device__ float g_S0[(size_t)BB*NN*MM];
__device__ float g_Fi[BB*MM];
__device__ int   g_ev[BB*MM];
__device__ float g_AO[(size_t)RR*DD];

// ---------------- SGEMM: C(RRxDD) = A(RRxDD) @ B(DDxDD), fp32 ----------------
// 64x64 block tile, BK=16, 256 threads, 4x4 micro-tile.
// scatterV=1 writes C into (B,H,N,Dh) head-major layout instead of row-major.
__global__ void __launch_bounds__(256) sgemm_kernel(
    const float* __restrict__ A, const float* __restrict__ B,
    float* __restrict__ C, int scatterV)
{
    __shared__ float As[64][17];
    __shared__ float Bs[16][64];
    int tid = threadIdx.x;
    int tx = tid & 15, ty = tid >> 4;
    int row0 = blockIdx.y * 64, col0 = blockIdx.x * 64;
    float acc[4][4] = {};
    int ar = tid >> 2, ac = (tid & 3) << 2;
    int br = tid >> 4, bc = (tid & 15) << 2;

    for (int k0 = 0; k0 < DD; k0 += 16) {
        float4 av = *(const float4*)(A + (size_t)(row0 + ar)*DD + k0 + ac);
        As[ar][ac+0] = av.x; As[ar][ac+1] = av.y; As[ar][ac+2] = av.z; As[ar][ac+3] = av.w;
        float4 bv = *(const float4*)(B + (size_t)(k0 + br)*DD + col0 + bc);
        *(float4*)&Bs[br][bc] = bv;
        __syncthreads();
#pragma unroll
        for (int k = 0; k < 16; ++k) {
            float a0 = As[ty*4+0][k], a1 = As[ty*4+1][k];
            float a2 = As[ty*4+2][k], a3 = As[ty*4+3][k];
            float4 b4 = *(const float4*)&Bs[k][tx*4];
            acc[0][0] += a0*b4.x; acc[0][1] += a0*b4.y; acc[0][2] += a0*b4.z; acc[0][3] += a0*b4.w;
            acc[1][0] += a1*b4.x; acc[1][1] += a1*b4.y; acc[1][2] += a1*b4.z; acc[1][3] += a1*b4.w;
            acc[2][0] += a2*b4.x; acc[2][1] += a2*b4.y; acc[2][2] += a2*b4.z; acc[2][3] += a2*b4.w;
            acc[3][0] += a3*b4.x; acc[3][1] += a3*b4.y; acc[3][2] += a3*b4.z; acc[3][3] += a3*b4.w;
        }
        __syncthreads();
    }
    if (!scatterV) {
#pragma unroll
        for (int i = 0; i < 4; ++i) {
            int r = row0 + ty*4 + i;
            float4 w = make_float4(acc[i][0], acc[i][1], acc[i][2], acc[i][3]);
            *(float4*)(C + (size_t)r*DD + col0 + tx*4) = w;
        }
    } else {
#pragma unroll
        for (int i = 0; i < 4; ++i) {
            int r = row0 + ty*4 + i;
            int c = col0 + tx*4;
            int b = r >> 11, n = r & (NN-1);
            int h = c >> 6,  dh = c & (DH-1);
            float4 w = make_float4(acc[i][0], acc[i][1], acc[i][2], acc[i][3]);
            *(float4*)(C + (((size_t)b*HH + h)*NN + n)*DH + dh) = w;
        }
    }
}

// ---------------- LayerNorm over D=1024 per row, scatter to (B,H,N,Dh) ----------------
__global__ void __launch_bounds__(256) ln_scatter_kernel(
    const float* __restrict__ Y, const float* __restrict__ gam,
    const float* __restrict__ bet, float* __restrict__ O)
{
    int row = blockIdx.x, t = threadIdx.x;
    const float* y = Y + (size_t)row * DD;
    float x0 = y[t], x1 = y[t+256], x2 = y[t+512], x3 = y[t+768];
    float s = x0+x1+x2+x3;
    float q = x0*x0 + x1*x1 + x2*x2 + x3*x3;
#pragma unroll
    for (int off = 16; off; off >>= 1) {
        s += __shfl_xor_sync(0xffffffffu, s, off);
        q += __shfl_xor_sync(0xffffffffu, q, off);
    }
    __shared__ float ss[8], sq[8];
    __shared__ float smu, srstd;
    if ((t & 31) == 0) { ss[t>>5] = s; sq[t>>5] = q; }
    __syncthreads();
    if (t == 0) {
        float S = 0.f, Q = 0.f;
#pragma unroll
        for (int i = 0; i < 8; ++i) { S += ss[i]; Q += sq[i]; }
        float mu = S * (1.0f/DD);
        float var = Q * (1.0f/DD) - mu*mu;
        smu = mu; srstd = rsqrtf(var + 1e-5f);
    }
    __syncthreads();
    float mu = smu, rs = srstd;
    int b = row >> 11, n = row & (NN-1);
    float xs[4] = {x0, x1, x2, x3};
#pragma unroll
    for (int i = 0; i < 4; ++i) {
        int d = t + i*256;
        float v = (xs[i] - mu) * rs * gam[d] + bet[d];
        O[(((size_t)b*HH + (d>>6))*NN + n)*DH + (d & (DH-1))] = v;
    }
}

// ---------------- S0[b,j,m] = relu(q0[j]·k0[m]/8), 0 if m==0 or m>=j ----------------
__global__ void __launch_bounds__(256) s0_kernel(
    const float* __restrict__ Qv, const float* __restrict__ Kv, float* __restrict__ S0)
{
    int b  = blockIdx.z;
    int j0 = blockIdx.y << 6, m0 = blockIdx.x << 6;
    int tid = threadIdx.x;
    size_t outbase = ((size_t)b*NN + j0)*MM + m0;
    if (m0 >= j0 + 64) {  // strictly upper-triangular tile: all-zero
        for (int idx = tid; idx < 4096; idx += 256) {
            int jj = idx >> 6, mm = idx & 63;
            S0[outbase + (size_t)jj*MM + mm] = 0.f;
        }
        return;
    }
    __shared__ float Qs[64][68];
    __shared__ float Kts[64][64];
    const float* Qb = Qv + (((size_t)b*HH + 0)*NN + j0)*DH;   // head 0
    const float* Kb = Kv + (((size_t)b*HH + 0)*NN + m0)*DH;
    int r = tid >> 2, c0 = (tid & 3) << 4;
#pragma unroll
    for (int u = 0; u < 4; ++u) {
        float4 v = *(const float4*)(Qb + (size_t)r*DH + c0 + u*4);
        Qs[r][c0+u*4+0] = v.x; Qs[r][c0+u*4+1] = v.y; Qs[r][c0+u*4+2] = v.z; Qs[r][c0+u*4+3] = v.w;
        float4 w = *(const float4*)(Kb + (size_t)r*DH + c0 + u*4);
        Kts[c0+u*4+0][r] = w.x; Kts[c0+u*4+1][r] = w.y; Kts[c0+u*4+2][r] = w.z; Kts[c0+u*4+3][r] = w.w;
    }
    __syncthreads();
    int tx = tid & 15, ty = tid >> 4;
    float acc[4][4] = {};
#pragma unroll 8
    for (int k = 0; k < 64; ++k) {
        float a0 = Qs[ty*4+0][k], a1 = Qs[ty*4+1][k];
        float a2 = Qs[ty*4+2][k], a3 = Qs[ty*4+3][k];
        float4 b4 = *(const float4*)&Kts[k][tx*4];
        acc[0][0] += a0*b4.x; acc[0][1] += a0*b4.y; acc[0][2] += a0*b4.z; acc[0][3] += a0*b4.w;
        acc[1][0] += a1*b4.x; acc[1][1] += a1*b4.y; acc[1][2] += a1*b4.z; acc[1][3] += a1*b4.w;
        acc[2][0] += a2*b4.x; acc[2][1] += a2*b4.y; acc[2][2] += a2*b4.z; acc[2][3] += a2*b4.w;
        acc[3][0] += a3*b4.x; acc[3][1] += a3*b4.y; acc[3][2] += a3*b4.z; acc[3][3] += a3*b4.w;
    }
#pragma unroll
    for (int i = 0; i < 4; ++i) {
        int j = j0 + ty*4 + i;
        int mb = m0 + tx*4;
        float4 w;
        w.x = ((mb+0) == 0 || (mb+0) >= j) ? 0.f : fmaxf(acc[i][0]*0.125f, 0.f);
        w.y = ((mb+1) == 0 || (mb+1) >= j) ? 0.f : fmaxf(acc[i][1]*0.125f, 0.f);
        w.z = ((mb+2) == 0 || (mb+2) >= j) ? 0.f : fmaxf(acc[i][2]*0.125f, 0.f);
        w.w = ((mb+3) == 0 || (mb+3) >= j) ? 0.f : fmaxf(acc[i][3]*0.125f, 0.f);
        *(float4*)(S0 + ((size_t)b*NN + j)*MM + mb) = w;
    }
}

// ---------------- Finit[b,m] = sum_{j<1024} S0[b,j,m]  (deterministic) ----------------
__global__ void __launch_bounds__(256) finit_kernel(
    const float* __restrict__ S0, float* __restrict__ Fi)
{
    int b = blockIdx.y;
    int col = (blockIdx.x << 6) + (threadIdx.x & 63);
    int part = threadIdx.x >> 6;             // 4 parts of 256 rows
    const float* base = S0 + ((size_t)b*NN + part*256)*MM + col;
    float s = 0.f;
#pragma unroll 4
    for (int r = 0; r < 256; ++r) s += base[(size_t)r*MM];
    __shared__ float ps[256];
    ps[threadIdx.x] = s;
    __syncthreads();
    if (threadIdx.x < 64) {
        Fi[b*MM + (blockIdx.x << 6) + threadIdx.x] =
            ps[threadIdx.x] + ps[threadIdx.x+64] + ps[threadIdx.x+128] + ps[threadIdx.x+192];
    }
}

// ---------------- serial heavy-hitter eviction scan (1 block per batch) ----------------
// Fact used: the newly inserted candidate i always has Fm score exactly 0 and ties break
// to earlier positions, so it is never evicted -> argmax over the 1024 resident keys only.
__global__ void __launch_bounds__(1024) scan_kernel(
    const float* __restrict__ S0, const float* __restrict__ Fi, int* __restrict__ evict)
{
    __shared__ float F[2048];
    __shared__ int unm[1024];
    __shared__ float wv[32];
    __shared__ int wp[32];
    __shared__ int s_idx;
    int b = blockIdx.x, t = threadIdx.x;
    F[t]        = Fi[b*MM + t];
    F[t + 1024] = Fi[b*MM + 1024 + t];
    unm[t] = t;
    evict[b*MM + t] = BIGV;
    evict[b*MM + 1024 + t] = BIGV;
    const float* Sb = S0 + (size_t)b*NN*MM;
    float r0 = 0.f, r1 = 0.f;          // row to add at this step (row i-1; none for i=1024)
    __syncthreads();
    for (int i = 1024; i < 2048; ++i) {
        F[t]        += r0;
        F[t + 1024] += r1;
        // prefetch row i (added at step i+1) while the reduction runs
        const float* nrow = Sb + (size_t)i*MM;
        r0 = nrow[t]; r1 = nrow[t + 1024];
        __syncthreads();
        // argmax over resident candidates, tie -> smallest position
        float v = F[unm[t]];
        int   p = t;
#pragma unroll
        for (int off = 16; off; off >>= 1) {
            float ov = __shfl_down_sync(0xffffffffu, v, off);
            int   op = __shfl_down_sync(0xffffffffu, p, off);
            if (ov > v || (ov == v && op < p)) { v = ov; p = op; }
        }
        if ((t & 31) == 0) { wv[t>>5] = v; wp[t>>5] = p; }
        __syncthreads();
        if (t < 32) {
            v = wv[t]; p = wp[t];
#pragma unroll
            for (int off = 16; off; off >>= 1) {
                float ov = __shfl_down_sync(0xffffffffu, v, off);
                int   op = __shfl_down_sync(0xffffffffu, p, off);
                if (ov > v || (ov == v && op < p)) { v = ov; p = op; }
            }
            if (t == 0) s_idx = p;
        }
        __syncthreads();
        int idx = s_idx;
        if (t == idx) evict[b*MM + unm[idx]] = i;
        int nv = (t < idx) ? unm[t] : (t < 1023 ? unm[t+1] : i);   // shift-left + append i
        __syncthreads();
        unm[t] = nv;
        __syncthreads();
    }
}

// ---------------- flash-style fp32 attention with causal + prune mask ----------------
__global__ void __launch_bounds__(256) attn_kernel(
    const float* __restrict__ Qv, const float* __restrict__ Kv,
    const float* __restrict__ Vv, const int* __restrict__ ev_g,
    float* __restrict__ AO)
{
    extern __shared__ float sm[];
    float* Qs  = sm;                 // 64x68
    float* Ps  = sm + 64*68;         // 64x68
    float* Kts = sm + 2*64*68;       // 64x64 (transposed: [k][m])
    float* Vs  = Kts + 64*64;        // 64x64
    int*   evs = (int*)(Vs + 64*64); // 64

    int bq = (int)gridDim.x - 1 - (int)blockIdx.x;  // heavy (late) tiles scheduled first
    int h = blockIdx.y, b = blockIdx.z;
    int nq0 = bq << 6;
    int tid = threadIdx.x;
    int tx = tid & 15, ty = tid >> 4;

    const float* Qb = Qv + (((size_t)b*HH + h)*NN + nq0)*DH;
    {
        int r = tid >> 2, c0 = (tid & 3) << 4;
#pragma unroll
        for (int u = 0; u < 4; ++u) {
            float4 v = *(const float4*)(Qb + (size_t)r*DH + c0 + u*4);
            Qs[r*68 + c0+u*4+0] = v.x; Qs[r*68 + c0+u*4+1] = v.y;
            Qs[r*68 + c0+u*4+2] = v.z; Qs[r*68 + c0+u*4+3] = v.w;
        }
    }
    float mrow[4], lrow[4], o[4][4];
#pragma unroll
    for (int i = 0; i < 4; ++i) {
        mrow[i] = -1e30f; lrow[i] = 0.f;
#pragma unroll
        for (int j = 0; j < 4; ++j) o[i][j] = 0.f;
    }

    for (int kt = 0; kt <= bq; ++kt) {
        int m0 = kt << 6;
        const float* Kb = Kv + (((size_t)b*HH + h)*NN + m0)*DH;
        const float* Vb = Vv + (((size_t)b*HH + h)*NN + m0)*DH;
        __syncthreads();   // previous tile's Kts/Vs/Ps reads are done
        {
            int r = tid >> 2, c0 = (tid & 3) << 4;
#pragma unroll
            for (int u = 0; u < 4; ++u) {
                float4 v = *(const float4*)(Kb + (size_t)r*DH + c0 + u*4);
                Kts[(c0+u*4+0)*64 + r] = v.x; Kts[(c0+u*4+1)*64 + r] = v.y;
                Kts[(c0+u*4+2)*64 + r] = v.z; Kts[(c0+u*4+3)*64 + r] = v.w;
                float4 w = *(const float4*)(Vb + (size_t)r*DH + c0 + u*4);
                *(float4*)&Vs[r*64 + c0 + u*4] = w;
            }
        }
        if (tid < 64) evs[tid] = ev_g[b*MM + m0 + tid];
        __syncthreads();

        // S = Q K^T
        float acc[4][4] = {};
#pragma unroll 8
        for (int k = 0; k < 64; ++k) {
            float a0 = Qs[(ty*4+0)*68 + k], a1 = Qs[(ty*4+1)*68 + k];
            float a2 = Qs[(ty*4+2)*68 + k], a3 = Qs[(ty*4+3)*68 + k];
            float4 b4 = *(const float4*)&Kts[k*64 + tx*4];
            acc[0][0] += a0*b4.x; acc[0][1] += a0*b4.y; acc[0][2] += a0*b4.z; acc[0][3] += a0*b4.w;
            acc[1][0] += a1*b4.x; acc[1][1] += a1*b4.y; acc[1][2] += a1*b4.z; acc[1][3] += a1*b4.w;
            acc[2][0] += a2*b4.x; acc[2][1] += a2*b4.y; acc[2][2] += a2*b4.z; acc[2][3] += a2*b4.w;
            acc[3][0] += a3*b4.x; acc[3][1] += a3*b4.y; acc[3][2] += a3*b4.z; acc[3][3] += a3*b4.w;
        }
        // mask: causal (m<=n) AND not-yet-evicted (n < evict_time[m])
        int ev4[4];
#pragma unroll
        for (int j = 0; j < 4; ++j) ev4[j] = evs[tx*4 + j];
#pragma unroll
        for (int i = 0; i < 4; ++i) {
            int n = nq0 + ty*4 + i;
#pragma unroll
            for (int j = 0; j < 4; ++j) {
                int m = m0 + tx*4 + j;
                bool keep = (m <= n) && (n < ev4[j]);
                acc[i][j] = keep ? acc[i][j]*0.125f : -1e30f;
            }
        }
        // online softmax (row stats via tx-shuffles, replicated)
#pragma unroll
        for (int i = 0; i < 4; ++i) {
            float tm = fmaxf(fmaxf(acc[i][0], acc[i][1]), fmaxf(acc[i][2], acc[i][3]));
#pragma unroll
            for (int off = 8; off; off >>= 1) tm = fmaxf(tm, __shfl_xor_sync(0xffffffffu, tm, off));
            float nm = fmaxf(mrow[i], tm);
            float alpha = __expf(mrow[i] - nm);
            float rsum = 0.f;
#pragma unroll
            for (int j = 0; j < 4; ++j) {
                float pv = (acc[i][j] <= -1e29f) ? 0.f : __expf(acc[i][j] - nm);
                Ps[(ty*4+i)*68 + tx*4 + j] = pv;
                rsum += pv;
            }
#pragma unroll
            for (int off = 8; off; off >>= 1) rsum += __shfl_xor_sync(0xffffffffu, rsum, off);
            lrow[i] = lrow[i]*alpha + rsum;
            mrow[i] = nm;
#pragma unroll
            for (int j = 0; j < 4; ++j) o[i][j] *= alpha;
        }
        __syncthreads();
        // O += P @ V
#pragma unroll 8
        for (int k = 0; k < 64; ++k) {
            float p0 = Ps[(ty*4+0)*68 + k], p1 = Ps[(ty*4+1)*68 + k];
            float p2 = Ps[(ty*4+2)*68 + k], p3 = Ps[(ty*4+3)*68 + k];
            float4 v = *(const float4*)&Vs[k*64 + tx*4];
            o[0][0] += p0*v.x; o[0][1] += p0*v.y; o[0][2] += p0*v.z; o[0][3] += p0*v.w;
            o[1][0] += p1*v.x; o[1][1] += p1*v.y; o[1][2] += p1*v.z; o[1][3] += p1*v.w;
            o[2][0] += p2*v.x; o[2][1] += p2*v.y; o[2][2] += p2*v.z; o[2][3] += p2*v.w;
            o[3][0] += p3*v.x; o[3][1] += p3*v.y; o[3][2] += p3*v.z; o[3][3] += p3*v.w;
        }
    }
#pragma unroll
    for (int i = 0; i < 4; ++i) {
        float rl = 1.0f / lrow[i];
        int n = nq0 + ty*4 + i;
        float4 w = make_float4(o[i][0]*rl, o[i][1]*rl, o[i][2]*rl, o[i][3]*rl);
        *(float4*)(AO + ((size_t)b*NN + n)*DD + h*DH + tx*4) = w;
    }
}

#define ATT_SMEM ((64*68*2 + 64*64*2)*4 + 64*4)

extern "C" void kernel_launch(void* const* d_in, const int* in_sizes, int n_in,
                              void* d_out, int out_size)
{
    (void)in_sizes; (void)n_in; (void)out_size;
    const float* X  = (const float*)d_in[0];
    const float* Wq = (const float*)d_in[1];
    const float* Wk = (const float*)d_in[2];
    const float* Wv = (const float*)d_in[3];
    const float* Wo = (const float*)d_in[4];
    const float* gq = (const float*)d_in[5];
    const float* bq = (const float*)d_in[6];
    const float* gk = (const float*)d_in[7];
    const float* bk = (const float*)d_in[8];
    // d_in[9..11]: cache_k, cache_v, start_pos — unused (start_pos = 0)
    float* out = (float*)d_out;

    float *Yq, *Yk, *Qp, *Kp, *Vp, *S0, *Fi, *AO; int* ev;
    cudaGetSymbolAddress((void**)&Yq, g_Yq);
    cudaGetSymbolAddress((void**)&Yk, g_Yk);
    cudaGetSymbolAddress((void**)&Qp, g_Q);
    cudaGetSymbolAddress((void**)&Kp, g_K);
    cudaGetSymbolAddress((void**)&Vp, g_V);
    cudaGetSymbolAddress((void**)&S0, g_S0);
    cudaGetSymbolAddress((void**)&Fi, g_Fi);
    cudaGetSymbolAddress((void**)&ev, g_ev);
    cudaGetSymbolAddress((void**)&AO, g_AO);

    cudaFuncSetAttribute(attn_kernel, cudaFuncAttributeMaxDynamicSharedMemorySize, ATT_SMEM);

    dim3 gg(DD/64, RR/64);
    sgemm_kernel<<<gg, 256>>>(X, Wq, Yq, 0);
    sgemm_kernel<<<gg, 256>>>(X, Wk, Yk, 0);
    sgemm_kernel<<<gg, 256>>>(X, Wv, Vp, 1);
    ln_scatter_kernel<<<RR, 256>>>(Yq, gq, bq, Qp);
    ln_scatter_kernel<<<RR, 256>>>(Yk, gk, bk, Kp);
    s0_kernel<<<dim3(MM/64, NN/64, BB), 256>>>(Qp, Kp, S0);
    finit_kernel<<<dim3(MM/64, BB), 256>>>(S0, Fi);
    scan_kernel<<<BB, 1024>>>(S0, Fi, ev);
    attn_kernel<<<dim3(NN/64, HH, BB), 256, ATT_SMEM>>>(Qp, Kp, Vp, ev, AO);
    sgemm_kernel<<<gg, 256>>>(AO, Wo, out, 0);
}